// round 1
// baseline (speedup 1.0000x reference)
#include <cuda_runtime.h>
#include <cuda_bf16.h>
#include <math.h>

#define V_SIZE 4096
#define H_SIZE 2048
#define BATCH  64
#define STEPS  100
#define KTOT   (V_SIZE + H_SIZE)   // 6144
#define SPLIT_H 8
#define SPLIT_V 4

// ---------------- device scratch (no allocations allowed) ----------------
__device__ float g_vv [V_SIZE * V_SIZE];   // symmetrized vis-vis (64MB)
__device__ float g_hh [H_SIZE * H_SIZE];   // symmetrized hid-hid (16MB)
__device__ float g_vht[H_SIZE * V_SIZE];   // vis_hid^T  [h][v]   (32MB)
__device__ float g_visA[BATCH * V_SIZE];
__device__ float g_visB[BATCH * V_SIZE];
__device__ float g_hidA[BATCH * H_SIZE];
__device__ float g_hidB[BATCH * H_SIZE];
__device__ float g_CH[SPLIT_H * BATCH * H_SIZE];  // hid gemm split-K slices
__device__ float g_CV[SPLIT_V * BATCH * V_SIZE];  // vis gemm split-K slices

// ---------------- f32x2 packed math helpers ----------------
__device__ __forceinline__ void fma2(unsigned long long& d,
                                     unsigned long long a,
                                     unsigned long long b) {
    asm("fma.rn.f32x2 %0, %1, %2, %0;" : "+l"(d) : "l"(a), "l"(b));
}
__device__ __forceinline__ unsigned long long pack2(float x, float y) {
    unsigned long long r;
    asm("mov.b64 %0, {%1, %2};" : "=l"(r) : "f"(x), "f"(y));
    return r;
}
__device__ __forceinline__ float2 unpack2(unsigned long long v) {
    float2 r;
    asm("mov.b64 {%0, %1}, %2;" : "=f"(r.x), "=f"(r.y) : "l"(v));
    return r;
}

// ---------------- prep kernels ----------------
// out = triu(raw,1) + triu(raw,1)^T  (zero diagonal)
__global__ void k_sym(const float* __restrict__ raw, float* __restrict__ out, int n) {
    int idx = blockIdx.x * blockDim.x + threadIdx.x;
    if (idx >= n * n) return;
    int i = idx / n;
    int j = idx - i * n;
    float v = 0.0f;
    if (i < j)      v = raw[idx];
    else if (i > j) v = raw[j * n + i];
    out[idx] = v;
}

// g_vht[h][v] = vis_hid[v][h]   (tiled transpose)
__global__ void k_transpose(const float* __restrict__ in, float* __restrict__ out) {
    __shared__ float tile[32][33];
    int x  = blockIdx.x * 32 + threadIdx.x;           // H index
    int yb = blockIdx.y * 32;                          // V base
#pragma unroll
    for (int j = 0; j < 32; j += 8)
        tile[threadIdx.y + j][threadIdx.x] =
            in[(size_t)(yb + threadIdx.y + j) * H_SIZE + x];
    __syncthreads();
    int x2  = blockIdx.y * 32 + threadIdx.x;           // V index (out col)
    int yb2 = blockIdx.x * 32;                          // H base (out row)
#pragma unroll
    for (int j = 0; j < 32; j += 8)
        out[(size_t)(yb2 + threadIdx.y + j) * V_SIZE + x2] =
            tile[threadIdx.x][threadIdx.y + j];
}

__global__ void k_init(const float* __restrict__ x,
                       float* __restrict__ vis, float* __restrict__ hid) {
    int idx = blockIdx.x * blockDim.x + threadIdx.x;
    if (idx < BATCH * V_SIZE) vis[idx] = x[idx];
    if (idx < BATCH * H_SIZE) hid[idx] = 0.5f;
}

// ---------------- fused dual GEMM ----------------
// C[64][N] partial slices: C = A1(64,K1)@W1(K1,N) + A2(64,K2)@W2(K2,N)
// split-K over blockIdx.z (kPerSlice per slice, multiple of 16).
// BM=64, BN=128, BK=16; 256 threads, each 8m x 4n, m-paired f32x2 accumulators.
__global__ __launch_bounds__(256)
void gemm_dual(const float* __restrict__ A1, const float* __restrict__ W1, int K1,
               const float* __restrict__ A2, const float* __restrict__ W2, int K2,
               float* __restrict__ Cbuf, int N, int kPerSlice) {
    __shared__ float As[16][68];    // [k][m], padded
    __shared__ float Bs[16][128];   // [k][n]

    const int tid = threadIdx.x;
    const int bn0 = blockIdx.x * 128;
    const int kbeg = blockIdx.z * kPerSlice;
    const int kend = kbeg + kPerSlice;

    const int tx = tid & 31;        // n group (32 x 4)
    const int ty = tid >> 5;        // m group (8 x 8)
    const int tm0 = ty * 8;
    const int tn0 = tx * 4;

    unsigned long long acc[4][4];   // [n j][m pair p]
#pragma unroll
    for (int j = 0; j < 4; j++)
#pragma unroll
        for (int p = 0; p < 4; p++) acc[j][p] = 0ull;

    const int am = tid >> 2;          // A row 0..63
    const int ak = (tid & 3) * 4;     // A k sub-col 0,4,8,12
    const int brow = tid >> 5;        // B row 0..7 (and +8)
    const int bcol = (tid & 31) * 4;  // B col

    for (int k0 = kbeg; k0 < kend; k0 += 16) {
        const float* A; const float* W; int kk0; int Kd;
        if (k0 < K1) { A = A1; W = W1; kk0 = k0;      Kd = K1; }
        else         { A = A2; W = W2; kk0 = k0 - K1; Kd = K2; }

        float4 av = *(const float4*)(A + (size_t)am * Kd + kk0 + ak);
        float4 b0 = *(const float4*)(W + (size_t)(kk0 + brow)     * N + bn0 + bcol);
        float4 b1 = *(const float4*)(W + (size_t)(kk0 + 8 + brow) * N + bn0 + bcol);

        __syncthreads();
        As[ak + 0][am] = av.x;
        As[ak + 1][am] = av.y;
        As[ak + 2][am] = av.z;
        As[ak + 3][am] = av.w;
        *(float4*)&Bs[brow][bcol]     = b0;
        *(float4*)&Bs[brow + 8][bcol] = b1;
        __syncthreads();

#pragma unroll
        for (int kk = 0; kk < 16; kk++) {
            const unsigned long long* ap =
                (const unsigned long long*)&As[kk][tm0];
            unsigned long long a0 = ap[0], a1 = ap[1], a2 = ap[2], a3 = ap[3];
            float4 bv = *(const float4*)&Bs[kk][tn0];
            unsigned long long bb0 = pack2(bv.x, bv.x);
            unsigned long long bb1 = pack2(bv.y, bv.y);
            unsigned long long bb2 = pack2(bv.z, bv.z);
            unsigned long long bb3 = pack2(bv.w, bv.w);
            fma2(acc[0][0], a0, bb0); fma2(acc[0][1], a1, bb0);
            fma2(acc[0][2], a2, bb0); fma2(acc[0][3], a3, bb0);
            fma2(acc[1][0], a0, bb1); fma2(acc[1][1], a1, bb1);
            fma2(acc[1][2], a2, bb1); fma2(acc[1][3], a3, bb1);
            fma2(acc[2][0], a0, bb2); fma2(acc[2][1], a1, bb2);
            fma2(acc[2][2], a2, bb2); fma2(acc[2][3], a3, bb2);
            fma2(acc[3][0], a0, bb3); fma2(acc[3][1], a1, bb3);
            fma2(acc[3][2], a2, bb3); fma2(acc[3][3], a3, bb3);
        }
    }

    float* Cz = Cbuf + (size_t)blockIdx.z * BATCH * N;
#pragma unroll
    for (int p = 0; p < 4; p++) {
        float2 v0 = unpack2(acc[0][p]);
        float2 v1 = unpack2(acc[1][p]);
        float2 v2 = unpack2(acc[2][p]);
        float2 v3 = unpack2(acc[3][p]);
        int row = tm0 + 2 * p;
        *(float4*)(Cz + (size_t)row * N + bn0 + tn0) =
            make_float4(v0.x, v1.x, v2.x, v3.x);
        *(float4*)(Cz + (size_t)(row + 1) * N + bn0 + tn0) =
            make_float4(v0.y, v1.y, v2.y, v3.y);
    }
}

// ---------------- epilogue: sum slices + bias, sigmoid(pre/temp), blend ----
__global__ void epilogue(const float* __restrict__ Cbuf, int S, int N,
                         const float* __restrict__ bias,
                         const float* __restrict__ oldv,
                         float* __restrict__ outv,
                         int step, const int* __restrict__ steps_ptr) {
    int idx = blockIdx.x * blockDim.x + threadIdx.x;
    if (idx >= BATCH * N) return;
    int n = idx % N;
    float s = 0.0f;
    for (int z = 0; z < S; z++) s += Cbuf[(size_t)z * BATCH * N + idx];
    s += bias[n];
    float stepsf = (float)(*steps_ptr);
    float temp = 0.01f * (1.0f + 4.0f * expf((-5.0f * (float)step) / stepsf));
    float p = 1.0f / (1.0f + expf(-s / temp));
    outv[idx] = 0.9f * oldv[idx] + 0.1f * p;
}

// ---------------- host launcher ----------------
extern "C" void kernel_launch(void* const* d_in, const int* in_sizes, int n_in,
                              void* d_out, int out_size) {
    const float* x        = (const float*)d_in[0];
    const float* vis_bias = (const float*)d_in[1];
    const float* hid_bias = (const float*)d_in[2];
    const float* vis_hid  = (const float*)d_in[3];
    const float* vv_raw   = (const float*)d_in[4];
    const float* hh_raw   = (const float*)d_in[5];
    const int*   steps_p  = (const int*)d_in[6];

    float *vv, *hh, *vht, *visA, *visB, *hidA, *hidB, *CH, *CV;
    cudaGetSymbolAddress((void**)&vv,  g_vv);
    cudaGetSymbolAddress((void**)&hh,  g_hh);
    cudaGetSymbolAddress((void**)&vht, g_vht);
    cudaGetSymbolAddress((void**)&visA, g_visA);
    cudaGetSymbolAddress((void**)&visB, g_visB);
    cudaGetSymbolAddress((void**)&hidA, g_hidA);
    cudaGetSymbolAddress((void**)&hidB, g_hidB);
    cudaGetSymbolAddress((void**)&CH,  g_CH);
    cudaGetSymbolAddress((void**)&CV,  g_CV);

    // prep: symmetrize couplings, transpose vis_hid, init state
    k_sym<<<(V_SIZE * V_SIZE + 255) / 256, 256>>>(vv_raw, vv, V_SIZE);
    k_sym<<<(H_SIZE * H_SIZE + 255) / 256, 256>>>(hh_raw, hh, H_SIZE);
    k_transpose<<<dim3(H_SIZE / 32, V_SIZE / 32), dim3(32, 8)>>>(vis_hid, vht);
    k_init<<<(BATCH * V_SIZE + 255) / 256, 256>>>(x, visA, hidA);

    float* visCur = visA;
    float* hidCur = hidA;
    for (int i = 0; i < STEPS; i++) {
        float* hidNext = (hidCur == hidA) ? hidB : hidA;
        float* visNext = (i == STEPS - 1) ? (float*)d_out
                                          : ((visCur == visA) ? visB : visA);

        // hidden update: pre = hid@hh + vis@vis_hid (+ hid_bias in epilogue)
        gemm_dual<<<dim3(H_SIZE / 128, 1, SPLIT_H), 256>>>(
            hidCur, hh, H_SIZE, visCur, vis_hid, V_SIZE,
            CH, H_SIZE, KTOT / SPLIT_H);
        epilogue<<<(BATCH * H_SIZE + 255) / 256, 256>>>(
            CH, SPLIT_H, H_SIZE, hid_bias, hidCur, hidNext, i, steps_p);

        // visible update: pre = vis@vv + hid_new@vis_hid^T (+ vis_bias)
        gemm_dual<<<dim3(V_SIZE / 128, 1, SPLIT_V), 256>>>(
            visCur, vv, V_SIZE, hidNext, vht, H_SIZE,
            CV, V_SIZE, KTOT / SPLIT_V);
        epilogue<<<(BATCH * V_SIZE + 255) / 256, 256>>>(
            CV, SPLIT_V, V_SIZE, vis_bias, visCur, visNext, i, steps_p);

        hidCur = hidNext;
        visCur = visNext;
    }
}

// round 3
// speedup vs baseline: 2.5104x; 2.5104x over previous
#include <cuda_runtime.h>
#include <cuda_fp16.h>
#include <stdint.h>
#include <math.h>

#define VS 4096
#define HS 2048
#define NB 64
#define STEPS 100
#define SPLIT_H 8
#define SPLIT_V 4
#define KTOT (VS + HS)

#define MT 128        // M tile (weight rows) per CTA
#define BK 32         // K tile
#define PITCH 40      // smem row pitch in halves (80B, conflict-free & 16B aligned)
#define WSCALE 64.0f
#define INV_WSCALE (1.0f/64.0f)

// ---------------- device scratch (no allocations allowed) ----------------
// weight limb arrays (fp16, pre-scaled by 64)
__device__ __half g_vv0[VS*VS], g_vv1[VS*VS];       // 32MB each
__device__ __half g_hh0[HS*HS], g_hh1[HS*HS];       // 8MB each
__device__ __half g_vh0[VS*HS], g_vh1[VS*HS];       // vis_hid [v][h]
__device__ __half g_vht0[HS*VS], g_vht1[HS*VS];     // vis_hid^T [h][v]
// states: fp32 in [feature][batch], fp16 limbs in [batch][feature]
__device__ float  g_visF[VS*NB], g_hidF[HS*NB];
__device__ __half g_visL0[NB*VS], g_visL1[NB*VS];
__device__ __half g_hidL0[NB*HS], g_hidL1[NB*HS];
// split-K slice buffers, layout [slice][feature][batch]
__device__ float g_D1[SPLIT_H*HS*NB];
__device__ float g_D2[SPLIT_V*VS*NB];

// ---------------- helpers ----------------
__device__ __forceinline__ uint32_t smaddr(const void* p) {
    return (uint32_t)__cvta_generic_to_shared(p);
}
__device__ __forceinline__ void cp16(uint32_t dst, const void* src) {
    asm volatile("cp.async.cg.shared.global [%0], [%1], 16;" :: "r"(dst), "l"(src));
}
__device__ __forceinline__ void split_w(float w, __half& h0, __half& h1) {
    float ws = w * WSCALE;
    h0 = __float2half_rn(ws);
    h1 = __float2half_rn(ws - __half2float(h0));
}

#define MMA_16816(dd, aa, b0r, b1r)                                          \
    asm volatile("mma.sync.aligned.m16n8k16.row.col.f32.f16.f16.f32 "        \
        "{%0,%1,%2,%3},{%4,%5,%6,%7},{%8,%9},{%0,%1,%2,%3};"                 \
        : "+f"(dd[0]), "+f"(dd[1]), "+f"(dd[2]), "+f"(dd[3])                 \
        : "r"(aa[0]), "r"(aa[1]), "r"(aa[2]), "r"(aa[3]), "r"(b0r), "r"(b1r))

// ---------------- prep kernels ----------------
// symmetrize (triu(raw,1)+triu(raw,1)^T), scale by 64, split to 2 fp16 limbs
__global__ void k_sym_split(const float* __restrict__ raw, int n,
                            __half* __restrict__ o0, __half* __restrict__ o1) {
    __shared__ float tA[32][33], tB[32][33];
    int bi = blockIdx.y * 32, bj = blockIdx.x * 32;
    int tx = threadIdx.x, ty = threadIdx.y;   // (32,8)
#pragma unroll
    for (int j = 0; j < 32; j += 8) {
        tA[ty + j][tx] = raw[(size_t)(bi + ty + j) * n + bj + tx];
        tB[ty + j][tx] = raw[(size_t)(bj + ty + j) * n + bi + tx];
    }
    __syncthreads();
#pragma unroll
    for (int j = 0; j < 32; j += 8) {
        int i = bi + ty + j, jj = bj + tx;
        float wv = (i < jj) ? tA[ty + j][tx] : ((i > jj) ? tB[tx][ty + j] : 0.0f);
        __half h0, h1; split_w(wv, h0, h1);
        o0[(size_t)i * n + jj] = h0;
        o1[(size_t)i * n + jj] = h1;
    }
}

// split vis_hid into limbs in both orientations
__global__ void k_vh_split(const float* __restrict__ vh,
                           __half* __restrict__ o0, __half* __restrict__ o1,
                           __half* __restrict__ t0, __half* __restrict__ t1) {
    __shared__ float tile[32][33];
    int bh = blockIdx.x * 32, bv = blockIdx.y * 32;
    int tx = threadIdx.x, ty = threadIdx.y;
#pragma unroll
    for (int j = 0; j < 32; j += 8)
        tile[ty + j][tx] = vh[(size_t)(bv + ty + j) * HS + bh + tx];
    __syncthreads();
#pragma unroll
    for (int j = 0; j < 32; j += 8) {
        __half h0, h1;
        split_w(tile[ty + j][tx], h0, h1);
        o0[(size_t)(bv + ty + j) * HS + bh + tx] = h0;
        o1[(size_t)(bv + ty + j) * HS + bh + tx] = h1;
        split_w(tile[tx][ty + j], h0, h1);           // vht[h][v] = vh[v][h]
        t0[(size_t)(bh + ty + j) * VS + bv + tx] = h0;
        t1[(size_t)(bh + ty + j) * VS + bv + tx] = h1;
    }
}

__global__ void k_init(const float* __restrict__ x,
                       float* __restrict__ visF, __half* __restrict__ vL0, __half* __restrict__ vL1,
                       float* __restrict__ hidF, __half* __restrict__ hL0, __half* __restrict__ hL1) {
    int idx = blockIdx.x * blockDim.x + threadIdx.x;
    if (idx < NB * VS) {
        int b = idx >> 12, v = idx & (VS - 1);
        float val = x[idx];                    // x[b][v]
        visF[v * NB + b] = val;
        __half h0 = __float2half_rn(val);
        __half h1 = __float2half_rn(val - __half2float(h0));
        vL0[idx] = h0; vL1[idx] = h1;
    }
    if (idx < NB * HS) {
        hidF[idx] = 0.5f;
        hL0[idx] = __float2half_rn(0.5f);
        hL1[idx] = __float2half_rn(0.0f);
    }
}

// ---------------- split-fp16 tensor-core dual GEMM ----------------
// D[m, b] (Mtot x 64) = sum_k Wlimbs[m,k] * Blimbs[b,k]   (3-product split fp16)
// K region 1: (A1, B1, K1), region 2: (A2, B2, K2). Split-K over blockIdx.z.
__global__ __launch_bounds__(256, 1)
void gemm_mma(const __half* __restrict__ A1_0, const __half* __restrict__ A1_1,
              const __half* __restrict__ B1_0, const __half* __restrict__ B1_1, int K1,
              const __half* __restrict__ A2_0, const __half* __restrict__ A2_1,
              const __half* __restrict__ B2_0, const __half* __restrict__ B2_1, int K2,
              float* __restrict__ Cbuf, int Mtot, int kPerSlice) {
    extern __shared__ __half sm[];
    const int ASZ = MT * PITCH;    // 5120 halves
    const int BSZ = NB * PITCH;    // 2560 halves
    __half* Abase = sm;            // [stage][limb][ASZ]
    __half* Bbase = sm + 4 * ASZ;  // [stage][limb][BSZ]

    const int tid = threadIdx.x;
    const int lane = tid & 31;
    const int w = tid >> 5;
    const int wm = (w & 3) * 32;   // warp M offset within 128
    const int wn = (w >> 2) * 32;  // warp N offset within 64
    const int m_blk = blockIdx.x * MT;
    const int kbeg = blockIdx.z * kPerSlice;
    const int ntiles = kPerSlice / BK;

    float d[2][4][4];
#pragma unroll
    for (int i = 0; i < 2; i++)
#pragma unroll
        for (int j = 0; j < 4; j++)
#pragma unroll
            for (int q = 0; q < 4; q++) d[i][j][q] = 0.0f;

    auto load_tile = [&](int t, int st) {
        int k0 = kbeg + t * BK;
        const __half *Aw0, *Aw1, *Bw0, *Bw1; int kk, ld;
        if (k0 < K1) { Aw0 = A1_0; Aw1 = A1_1; Bw0 = B1_0; Bw1 = B1_1; kk = k0;      ld = K1; }
        else         { Aw0 = A2_0; Aw1 = A2_1; Bw0 = B2_0; Bw1 = B2_1; kk = k0 - K1; ld = K2; }
        __half* Ast = Abase + st * 2 * ASZ;
        __half* Bst = Bbase + st * 2 * BSZ;
#pragma unroll
        for (int i = 0; i < 4; i++) {          // A: 128 rows x 4 chunks x 2 limbs
            int c = tid + i * 256;
            int limb = c >> 9;
            int row = (c >> 2) & 127;
            int col = (c & 3) * 8;
            const __half* src = (limb ? Aw1 : Aw0) + (size_t)(m_blk + row) * ld + kk + col;
            cp16(smaddr(Ast + limb * ASZ + row * PITCH + col), src);
        }
#pragma unroll
        for (int i = 0; i < 2; i++) {          // B: 64 rows x 4 chunks x 2 limbs
            int c = tid + i * 256;
            int limb = c >> 8;
            int row = (c >> 2) & 63;
            int col = (c & 3) * 8;
            const __half* src = (limb ? Bw1 : Bw0) + (size_t)row * ld + kk + col;
            cp16(smaddr(Bst + limb * BSZ + row * PITCH + col), src);
        }
        asm volatile("cp.async.commit_group;");
    };

    load_tile(0, 0);

    for (int t = 0; t < ntiles; t++) {
        if (t + 1 < ntiles) {
            load_tile(t + 1, (t + 1) & 1);
            asm volatile("cp.async.wait_group 1;");
        } else {
            asm volatile("cp.async.wait_group 0;");
        }
        __syncthreads();
        const __half* Ast = Abase + (t & 1) * 2 * ASZ;
        const __half* Bst = Bbase + (t & 1) * 2 * BSZ;
#pragma unroll
        for (int ks = 0; ks < BK; ks += 16) {
            uint32_t af[2][2][4];   // [mtile][limb][4]
#pragma unroll
            for (int mt = 0; mt < 2; mt++) {
                int row = wm + mt * 16 + ((lane >> 3) & 1) * 8 + (lane & 7);
                int kcol = ks + (lane >> 4) * 8;
#pragma unroll
                for (int limb = 0; limb < 2; limb++) {
                    uint32_t a = smaddr(Ast + limb * ASZ + row * PITCH + kcol);
                    asm volatile("ldmatrix.sync.aligned.m8n8.x4.shared.b16 {%0,%1,%2,%3},[%4];"
                        : "=r"(af[mt][limb][0]), "=r"(af[mt][limb][1]),
                          "=r"(af[mt][limb][2]), "=r"(af[mt][limb][3]) : "r"(a));
                }
            }
            uint32_t bf[2][8];      // [limb][n8tile j: regs 2j,2j+1]
#pragma unroll
            for (int nt = 0; nt < 2; nt++) {
                int row = wn + nt * 16 + (lane >> 4) * 8 + (lane & 7);
                int kcol = ks + ((lane >> 3) & 1) * 8;
#pragma unroll
                for (int limb = 0; limb < 2; limb++) {
                    uint32_t a = smaddr(Bst + limb * BSZ + row * PITCH + kcol);
                    asm volatile("ldmatrix.sync.aligned.m8n8.x4.shared.b16 {%0,%1,%2,%3},[%4];"
                        : "=r"(bf[limb][nt * 4 + 0]), "=r"(bf[limb][nt * 4 + 1]),
                          "=r"(bf[limb][nt * 4 + 2]), "=r"(bf[limb][nt * 4 + 3]) : "r"(a));
                }
            }
#pragma unroll
            for (int mt = 0; mt < 2; mt++) {
#pragma unroll
                for (int j = 0; j < 4; j++) {
                    float* dd = d[mt][j];
                    uint32_t b00 = bf[0][j * 2], b01 = bf[0][j * 2 + 1];
                    uint32_t b10 = bf[1][j * 2], b11 = bf[1][j * 2 + 1];
                    MMA_16816(dd, af[mt][0], b00, b01);   // w0*b0
                    MMA_16816(dd, af[mt][0], b10, b11);   // w0*b1
                    MMA_16816(dd, af[mt][1], b00, b01);   // w1*b0
                }
            }
        }
        __syncthreads();
    }

    float* Cz = Cbuf + (size_t)blockIdx.z * Mtot * NB;
#pragma unroll
    for (int mt = 0; mt < 2; mt++) {
#pragma unroll
        for (int j = 0; j < 4; j++) {
            int r = m_blk + wm + mt * 16 + (lane >> 2);
            int c = wn + j * 8 + (lane & 3) * 2;
            *(float2*)&Cz[(size_t)r * NB + c]       = make_float2(d[mt][j][0], d[mt][j][1]);
            *(float2*)&Cz[(size_t)(r + 8) * NB + c] = make_float2(d[mt][j][2], d[mt][j][3]);
        }
    }
}

// ---------------- epilogue ----------------
__global__ void epi(const float* __restrict__ Cbuf, int S, int F,
                    const float* __restrict__ bias,
                    float* __restrict__ stateF,
                    __half* __restrict__ L0, __half* __restrict__ L1,
                    int step, const int* __restrict__ steps_ptr,
                    float* __restrict__ finout) {
    int idx = blockIdx.x * blockDim.x + threadIdx.x;
    if (idx >= F * NB) return;
    int f = idx >> 6, b = idx & 63;
    float s = 0.0f;
    for (int z = 0; z < S; z++) s += Cbuf[(size_t)z * F * NB + idx];
    s = s * INV_WSCALE + bias[f];
    float stepsf = (float)(*steps_ptr);
    float temp = 0.01f * (1.0f + 4.0f * expf((-5.0f * (float)step) / stepsf));
    float p = 1.0f / (1.0f + expf(-s / temp));
    float nv = 0.9f * stateF[idx] + 0.1f * p;
    stateF[idx] = nv;
    __half h0 = __float2half_rn(nv);
    __half h1 = __float2half_rn(nv - __half2float(h0));
    L0[(size_t)b * F + f] = h0;
    L1[(size_t)b * F + f] = h1;
    if (finout) finout[(size_t)b * F + f] = nv;
}

// ---------------- host launcher ----------------
extern "C" void kernel_launch(void* const* d_in, const int* in_sizes, int n_in,
                              void* d_out, int out_size) {
    const float* x        = (const float*)d_in[0];
    const float* vis_bias = (const float*)d_in[1];
    const float* hid_bias = (const float*)d_in[2];
    const float* vis_hid  = (const float*)d_in[3];
    const float* vv_raw   = (const float*)d_in[4];
    const float* hh_raw   = (const float*)d_in[5];
    const int*   steps_p  = (const int*)d_in[6];

    __half *vv0, *vv1, *hh0, *hh1, *vh0, *vh1, *vht0, *vht1;
    __half *visL0, *visL1, *hidL0, *hidL1;
    float *visF, *hidF, *D1, *D2;
    cudaGetSymbolAddress((void**)&vv0, g_vv0);   cudaGetSymbolAddress((void**)&vv1, g_vv1);
    cudaGetSymbolAddress((void**)&hh0, g_hh0);   cudaGetSymbolAddress((void**)&hh1, g_hh1);
    cudaGetSymbolAddress((void**)&vh0, g_vh0);   cudaGetSymbolAddress((void**)&vh1, g_vh1);
    cudaGetSymbolAddress((void**)&vht0, g_vht0); cudaGetSymbolAddress((void**)&vht1, g_vht1);
    cudaGetSymbolAddress((void**)&visF, g_visF); cudaGetSymbolAddress((void**)&hidF, g_hidF);
    cudaGetSymbolAddress((void**)&visL0, g_visL0); cudaGetSymbolAddress((void**)&visL1, g_visL1);
    cudaGetSymbolAddress((void**)&hidL0, g_hidL0); cudaGetSymbolAddress((void**)&hidL1, g_hidL1);
    cudaGetSymbolAddress((void**)&D1, g_D1);     cudaGetSymbolAddress((void**)&D2, g_D2);

    const int SMEM = (4 * MT * PITCH + 4 * NB * PITCH) * (int)sizeof(__half);  // 61440
    cudaFuncSetAttribute(gemm_mma, cudaFuncAttributeMaxDynamicSharedMemorySize, SMEM);

    // prep: symmetrize+split couplings, split vis_hid both ways, init state
    k_sym_split<<<dim3(VS / 32, VS / 32), dim3(32, 8)>>>(vv_raw, VS, vv0, vv1);
    k_sym_split<<<dim3(HS / 32, HS / 32), dim3(32, 8)>>>(hh_raw, HS, hh0, hh1);
    k_vh_split<<<dim3(HS / 32, VS / 32), dim3(32, 8)>>>(vis_hid, vh0, vh1, vht0, vht1);
    k_init<<<(NB * VS + 255) / 256, 256>>>(x, visF, visL0, visL1, hidF, hidL0, hidL1);

    for (int i = 0; i < STEPS; i++) {
        // hidden update: D1[h,b] = vht@vis^T + hh@hid^T
        gemm_mma<<<dim3(HS / MT, 1, SPLIT_H), 256, SMEM>>>(
            vht0, vht1, visL0, visL1, VS,
            hh0, hh1, hidL0, hidL1, HS,
            D1, HS, KTOT / SPLIT_H);
        epi<<<(HS * NB + 255) / 256, 256>>>(
            D1, SPLIT_H, HS, hid_bias, hidF, hidL0, hidL1, i, steps_p, nullptr);

        // visible update: D2[v,b] = vv@vis^T + vis_hid@hid_new^T
        gemm_mma<<<dim3(VS / MT, 1, SPLIT_V), 256, SMEM>>>(
            vv0, vv1, visL0, visL1, VS,
            vh0, vh1, hidL0, hidL1, HS,
            D2, VS, KTOT / SPLIT_V);
        epi<<<(VS * NB + 255) / 256, 256>>>(
            D2, SPLIT_V, VS, vis_bias, visF, visL0, visL1, i, steps_p,
            (i == STEPS - 1) ? (float*)d_out : nullptr);
    }
}

// round 4
// speedup vs baseline: 2.8421x; 1.1321x over previous
#include <cuda_runtime.h>
#include <cuda_fp16.h>
#include <stdint.h>
#include <math.h>

#define VS 4096
#define HS 2048
#define NB 64
#define STEPS 100
#define SPLIT_H 16
#define SPLIT_V 8
#define KTOT (VS + HS)

#define MT 128        // M tile (weight rows) per CTA
#define BK 32         // K tile
#define NSTAGE 3
#define PITCH 40      // smem row pitch in halves (80B, conflict-free & 16B aligned)
#define WSCALE 64.0f
#define INV_WSCALE (1.0f/64.0f)

// ---------------- device scratch (no allocations allowed) ----------------
__device__ __half g_vv0[VS*VS], g_vv1[VS*VS];       // 32MB each
__device__ __half g_hh0[HS*HS], g_hh1[HS*HS];       // 8MB each
__device__ __half g_vh0[VS*HS], g_vh1[VS*HS];       // vis_hid [v][h]
__device__ __half g_vht0[HS*VS], g_vht1[HS*VS];     // vis_hid^T [h][v]
__device__ float  g_visF[VS*NB], g_hidF[HS*NB];
__device__ __half g_visL0[NB*VS], g_visL1[NB*VS];
__device__ __half g_hidL0[NB*HS], g_hidL1[NB*HS];
__device__ float g_D1[SPLIT_H*HS*NB];
__device__ float g_D2[SPLIT_V*VS*NB];

// ---------------- helpers ----------------
__device__ __forceinline__ uint32_t smaddr(const void* p) {
    return (uint32_t)__cvta_generic_to_shared(p);
}
__device__ __forceinline__ void cp16(uint32_t dst, const void* src) {
    asm volatile("cp.async.cg.shared.global [%0], [%1], 16;" :: "r"(dst), "l"(src));
}
__device__ __forceinline__ void split_w(float w, __half& h0, __half& h1) {
    float ws = w * WSCALE;
    h0 = __float2half_rn(ws);
    h1 = __float2half_rn(ws - __half2float(h0));
}

#define MMA_16816(dd, aa, b0r, b1r)                                          \
    asm volatile("mma.sync.aligned.m16n8k16.row.col.f32.f16.f16.f32 "        \
        "{%0,%1,%2,%3},{%4,%5,%6,%7},{%8,%9},{%0,%1,%2,%3};"                 \
        : "+f"(dd[0]), "+f"(dd[1]), "+f"(dd[2]), "+f"(dd[3])                 \
        : "r"(aa[0]), "r"(aa[1]), "r"(aa[2]), "r"(aa[3]), "r"(b0r), "r"(b1r))

// ---------------- prep kernels ----------------
__global__ void k_sym_split(const float* __restrict__ raw, int n,
                            __half* __restrict__ o0, __half* __restrict__ o1) {
    __shared__ float tA[32][33], tB[32][33];
    int bi = blockIdx.y * 32, bj = blockIdx.x * 32;
    int tx = threadIdx.x, ty = threadIdx.y;   // (32,8)
#pragma unroll
    for (int j = 0; j < 32; j += 8) {
        tA[ty + j][tx] = raw[(size_t)(bi + ty + j) * n + bj + tx];
        tB[ty + j][tx] = raw[(size_t)(bj + ty + j) * n + bi + tx];
    }
    __syncthreads();
#pragma unroll
    for (int j = 0; j < 32; j += 8) {
        int i = bi + ty + j, jj = bj + tx;
        float wv = (i < jj) ? tA[ty + j][tx] : ((i > jj) ? tB[tx][ty + j] : 0.0f);
        __half h0, h1; split_w(wv, h0, h1);
        o0[(size_t)i * n + jj] = h0;
        o1[(size_t)i * n + jj] = h1;
    }
}

__global__ void k_vh_split(const float* __restrict__ vh,
                           __half* __restrict__ o0, __half* __restrict__ o1,
                           __half* __restrict__ t0, __half* __restrict__ t1) {
    __shared__ float tile[32][33];
    int bh = blockIdx.x * 32, bv = blockIdx.y * 32;
    int tx = threadIdx.x, ty = threadIdx.y;
#pragma unroll
    for (int j = 0; j < 32; j += 8)
        tile[ty + j][tx] = vh[(size_t)(bv + ty + j) * HS + bh + tx];
    __syncthreads();
#pragma unroll
    for (int j = 0; j < 32; j += 8) {
        __half h0, h1;
        split_w(tile[ty + j][tx], h0, h1);
        o0[(size_t)(bv + ty + j) * HS + bh + tx] = h0;
        o1[(size_t)(bv + ty + j) * HS + bh + tx] = h1;
        split_w(tile[tx][ty + j], h0, h1);
        t0[(size_t)(bh + ty + j) * VS + bv + tx] = h0;
        t1[(size_t)(bh + ty + j) * VS + bv + tx] = h1;
    }
}

__global__ void k_init(const float* __restrict__ x,
                       float* __restrict__ visF, __half* __restrict__ vL0, __half* __restrict__ vL1,
                       float* __restrict__ hidF, __half* __restrict__ hL0, __half* __restrict__ hL1) {
    int idx = blockIdx.x * blockDim.x + threadIdx.x;
    if (idx < NB * VS) {
        int b = idx >> 12, v = idx & (VS - 1);
        float val = x[idx];
        visF[v * NB + b] = val;
        __half h0 = __float2half_rn(val);
        __half h1 = __float2half_rn(val - __half2float(h0));
        vL0[idx] = h0; vL1[idx] = h1;
    }
    if (idx < NB * HS) {
        hidF[idx] = 0.5f;
        hL0[idx] = __float2half_rn(0.5f);
        hL1[idx] = __float2half_rn(0.0f);
    }
}

// ---------------- split-fp16 tensor-core dual GEMM ----------------
__global__ __launch_bounds__(256, 2)
void gemm_mma(const __half* __restrict__ A1_0, const __half* __restrict__ A1_1,
              const __half* __restrict__ B1_0, const __half* __restrict__ B1_1, int K1,
              const __half* __restrict__ A2_0, const __half* __restrict__ A2_1,
              const __half* __restrict__ B2_0, const __half* __restrict__ B2_1, int K2,
              float* __restrict__ Cbuf, int Mtot, int kPerSlice) {
    extern __shared__ __half sm[];
    const int ASZ = MT * PITCH;    // 5120 halves
    const int BSZ = NB * PITCH;    // 2560 halves
    const int STG = 2 * (ASZ + BSZ);  // halves per stage (A limbs + B limbs)

    const int tid = threadIdx.x;
    const int lane = tid & 31;
    const int w = tid >> 5;
    const int wm = (w & 3) * 32;
    const int wn = (w >> 2) * 32;
    const int m_blk = blockIdx.x * MT;
    const int kbeg = blockIdx.z * kPerSlice;
    const int ntiles = kPerSlice / BK;

    float d[2][4][4];
#pragma unroll
    for (int i = 0; i < 2; i++)
#pragma unroll
        for (int j = 0; j < 4; j++)
#pragma unroll
            for (int q = 0; q < 4; q++) d[i][j][q] = 0.0f;

    auto load_tile = [&](int t, int st) {
        int k0 = kbeg + t * BK;
        const __half *Aw0, *Aw1, *Bw0, *Bw1; int kk, ld;
        if (k0 < K1) { Aw0 = A1_0; Aw1 = A1_1; Bw0 = B1_0; Bw1 = B1_1; kk = k0;      ld = K1; }
        else         { Aw0 = A2_0; Aw1 = A2_1; Bw0 = B2_0; Bw1 = B2_1; kk = k0 - K1; ld = K2; }
        __half* Ast = sm + st * STG;
        __half* Bst = Ast + 2 * ASZ;
#pragma unroll
        for (int i = 0; i < 4; i++) {          // A: 128 rows x 4 chunks x 2 limbs
            int c = tid + i * 256;
            int limb = c >> 9;
            int row = (c >> 2) & 127;
            int col = (c & 3) * 8;
            const __half* src = (limb ? Aw1 : Aw0) + (size_t)(m_blk + row) * ld + kk + col;
            cp16(smaddr(Ast + limb * ASZ + row * PITCH + col), src);
        }
#pragma unroll
        for (int i = 0; i < 2; i++) {          // B: 64 rows x 4 chunks x 2 limbs
            int c = tid + i * 256;
            int limb = c >> 8;
            int row = (c >> 2) & 63;
            int col = (c & 3) * 8;
            const __half* src = (limb ? Bw1 : Bw0) + (size_t)row * ld + kk + col;
            cp16(smaddr(Bst + limb * BSZ + row * PITCH + col), src);
        }
        asm volatile("cp.async.commit_group;");
    };

    load_tile(0, 0);
    if (ntiles > 1) load_tile(1, 1);

    for (int t = 0; t < ntiles; t++) {
        if (t + 2 < ntiles) {
            load_tile(t + 2, (t + 2) % NSTAGE);
            asm volatile("cp.async.wait_group 2;");
        } else if (t + 1 < ntiles) {
            asm volatile("cp.async.wait_group 1;");
        } else {
            asm volatile("cp.async.wait_group 0;");
        }
        __syncthreads();
        const __half* Ast = sm + (t % NSTAGE) * STG;
        const __half* Bst = Ast + 2 * ASZ;
#pragma unroll
        for (int ks = 0; ks < BK; ks += 16) {
            uint32_t af[2][2][4];
#pragma unroll
            for (int mt = 0; mt < 2; mt++) {
                int row = wm + mt * 16 + ((lane >> 3) & 1) * 8 + (lane & 7);
                int kcol = ks + (lane >> 4) * 8;
#pragma unroll
                for (int limb = 0; limb < 2; limb++) {
                    uint32_t a = smaddr(Ast + limb * ASZ + row * PITCH + kcol);
                    asm volatile("ldmatrix.sync.aligned.m8n8.x4.shared.b16 {%0,%1,%2,%3},[%4];"
                        : "=r"(af[mt][limb][0]), "=r"(af[mt][limb][1]),
                          "=r"(af[mt][limb][2]), "=r"(af[mt][limb][3]) : "r"(a));
                }
            }
            uint32_t bf[2][8];
#pragma unroll
            for (int nt = 0; nt < 2; nt++) {
                int row = wn + nt * 16 + (lane >> 4) * 8 + (lane & 7);
                int kcol = ks + ((lane >> 3) & 1) * 8;
#pragma unroll
                for (int limb = 0; limb < 2; limb++) {
                    uint32_t a = smaddr(Bst + limb * BSZ + row * PITCH + kcol);
                    asm volatile("ldmatrix.sync.aligned.m8n8.x4.shared.b16 {%0,%1,%2,%3},[%4];"
                        : "=r"(bf[limb][nt * 4 + 0]), "=r"(bf[limb][nt * 4 + 1]),
                          "=r"(bf[limb][nt * 4 + 2]), "=r"(bf[limb][nt * 4 + 3]) : "r"(a));
                }
            }
#pragma unroll
            for (int mt = 0; mt < 2; mt++) {
#pragma unroll
                for (int j = 0; j < 4; j++) {
                    float* dd = d[mt][j];
                    uint32_t b00 = bf[0][j * 2], b01 = bf[0][j * 2 + 1];
                    uint32_t b10 = bf[1][j * 2], b11 = bf[1][j * 2 + 1];
                    MMA_16816(dd, af[mt][0], b00, b01);   // w0*b0
                    MMA_16816(dd, af[mt][0], b10, b11);   // w0*b1
                    MMA_16816(dd, af[mt][1], b00, b01);   // w1*b0
                }
            }
        }
        __syncthreads();
    }

    float* Cz = Cbuf + (size_t)blockIdx.z * Mtot * NB;
#pragma unroll
    for (int mt = 0; mt < 2; mt++) {
#pragma unroll
        for (int j = 0; j < 4; j++) {
            int r = m_blk + wm + mt * 16 + (lane >> 2);
            int c = wn + j * 8 + (lane & 3) * 2;
            *(float2*)&Cz[(size_t)r * NB + c]       = make_float2(d[mt][j][0], d[mt][j][1]);
            *(float2*)&Cz[(size_t)(r + 8) * NB + c] = make_float2(d[mt][j][2], d[mt][j][3]);
        }
    }
}

// ---------------- epilogue ----------------
__global__ void epi(const float* __restrict__ Cbuf, int S, int F,
                    const float* __restrict__ bias,
                    float* __restrict__ stateF,
                    __half* __restrict__ L0, __half* __restrict__ L1,
                    int step, const int* __restrict__ steps_ptr,
                    float* __restrict__ finout) {
    int idx = blockIdx.x * blockDim.x + threadIdx.x;
    if (idx >= F * NB) return;
    int f = idx >> 6, b = idx & 63;
    float s = 0.0f;
    for (int z = 0; z < S; z++) s += Cbuf[(size_t)z * F * NB + idx];
    s = s * INV_WSCALE + bias[f];
    float stepsf = (float)(*steps_ptr);
    float temp = 0.01f * (1.0f + 4.0f * expf((-5.0f * (float)step) / stepsf));
    float p = 1.0f / (1.0f + expf(-s / temp));
    float nv = 0.9f * stateF[idx] + 0.1f * p;
    stateF[idx] = nv;
    __half h0 = __float2half_rn(nv);
    __half h1 = __float2half_rn(nv - __half2float(h0));
    L0[(size_t)b * F + f] = h0;
    L1[(size_t)b * F + f] = h1;
    if (finout) finout[(size_t)b * F + f] = nv;
}

// ---------------- host launcher ----------------
extern "C" void kernel_launch(void* const* d_in, const int* in_sizes, int n_in,
                              void* d_out, int out_size) {
    const float* x        = (const float*)d_in[0];
    const float* vis_bias = (const float*)d_in[1];
    const float* hid_bias = (const float*)d_in[2];
    const float* vis_hid  = (const float*)d_in[3];
    const float* vv_raw   = (const float*)d_in[4];
    const float* hh_raw   = (const float*)d_in[5];
    const int*   steps_p  = (const int*)d_in[6];

    __half *vv0, *vv1, *hh0, *hh1, *vh0, *vh1, *vht0, *vht1;
    __half *visL0, *visL1, *hidL0, *hidL1;
    float *visF, *hidF, *D1, *D2;
    cudaGetSymbolAddress((void**)&vv0, g_vv0);   cudaGetSymbolAddress((void**)&vv1, g_vv1);
    cudaGetSymbolAddress((void**)&hh0, g_hh0);   cudaGetSymbolAddress((void**)&hh1, g_hh1);
    cudaGetSymbolAddress((void**)&vh0, g_vh0);   cudaGetSymbolAddress((void**)&vh1, g_vh1);
    cudaGetSymbolAddress((void**)&vht0, g_vht0); cudaGetSymbolAddress((void**)&vht1, g_vht1);
    cudaGetSymbolAddress((void**)&visF, g_visF); cudaGetSymbolAddress((void**)&hidF, g_hidF);
    cudaGetSymbolAddress((void**)&visL0, g_visL0); cudaGetSymbolAddress((void**)&visL1, g_visL1);
    cudaGetSymbolAddress((void**)&hidL0, g_hidL0); cudaGetSymbolAddress((void**)&hidL1, g_hidL1);
    cudaGetSymbolAddress((void**)&D1, g_D1);     cudaGetSymbolAddress((void**)&D2, g_D2);

    const int SMEM = NSTAGE * 2 * (MT * PITCH + NB * PITCH) * (int)sizeof(__half);  // 92160
    cudaFuncSetAttribute(gemm_mma, cudaFuncAttributeMaxDynamicSharedMemorySize, SMEM);

    k_sym_split<<<dim3(VS / 32, VS / 32), dim3(32, 8)>>>(vv_raw, VS, vv0, vv1);
    k_sym_split<<<dim3(HS / 32, HS / 32), dim3(32, 8)>>>(hh_raw, HS, hh0, hh1);
    k_vh_split<<<dim3(HS / 32, VS / 32), dim3(32, 8)>>>(vis_hid, vh0, vh1, vht0, vht1);
    k_init<<<(NB * VS + 255) / 256, 256>>>(x, visF, visL0, visL1, hidF, hidL0, hidL1);

    for (int i = 0; i < STEPS; i++) {
        // hidden update: D1[h,b] = vht@vis^T + hh@hid^T
        gemm_mma<<<dim3(HS / MT, 1, SPLIT_H), 256, SMEM>>>(
            vht0, vht1, visL0, visL1, VS,
            hh0, hh1, hidL0, hidL1, HS,
            D1, HS, KTOT / SPLIT_H);
        epi<<<(HS * NB + 255) / 256, 256>>>(
            D1, SPLIT_H, HS, hid_bias, hidF, hidL0, hidL1, i, steps_p, nullptr);

        // visible update: D2[v,b] = vv@vis^T + vis_hid@hid_new^T
        gemm_mma<<<dim3(VS / MT, 1, SPLIT_V), 256, SMEM>>>(
            vv0, vv1, visL0, visL1, VS,
            vh0, vh1, hidL0, hidL1, HS,
            D2, VS, KTOT / SPLIT_V);
        epi<<<(VS * NB + 255) / 256, 256>>>(
            D2, SPLIT_V, VS, vis_bias, visF, visL0, visL1, i, steps_p,
            (i == STEPS - 1) ? (float*)d_out : nullptr);
    }
}

// round 5
// speedup vs baseline: 3.5697x; 1.2560x over previous
#include <cuda_runtime.h>
#include <cuda.h>
#include <cuda_fp16.h>
#include <stdint.h>
#include <math.h>

#define VS 4096
#define HS 2048
#define NB 64
#define STEPS 100
#define SPLIT_H 16
#define SPLIT_V 8
#define KTOT (VS + HS)

#define MT 128        // M tile per CTA
#define BKT 64        // K per tile (64 halves = 128B rows, SW128)
#define NSTAGE 2
#define WSCALE 64.0f
#define INV_WSCALE (1.0f/64.0f)

#define A_LIMB_BYTES (MT * BKT * 2)            // 16384
#define B_LIMB_BYTES (NB * BKT * 2)            // 8192
#define STAGE_BYTES  (2*A_LIMB_BYTES + 2*B_LIMB_BYTES)  // 49152

// ---------------- device scratch ----------------
__device__ __align__(1024) __half g_Wv0[(size_t)VS*KTOT], g_Wv1[(size_t)VS*KTOT]; // [v][vv|vh]
__device__ __align__(1024) __half g_Wh0[(size_t)HS*KTOT], g_Wh1[(size_t)HS*KTOT]; // [h][vht|hh]
__device__ __align__(1024) __half g_S0[NB*KTOT], g_S1[NB*KTOT];                   // [b][vis|hid]
__device__ float g_visF[VS*NB], g_hidF[HS*NB];     // fp32 state [feature][batch]
__device__ float g_D1[SPLIT_H*HS*NB];
__device__ float g_D2[SPLIT_V*VS*NB];

// ---------------- helpers ----------------
__device__ __forceinline__ uint32_t smaddr(const void* p) {
    return (uint32_t)__cvta_generic_to_shared(p);
}
__device__ __forceinline__ void split_w(float w, __half& h0, __half& h1) {
    float ws = w * WSCALE;
    h0 = __float2half_rn(ws);
    h1 = __float2half_rn(ws - __half2float(h0));
}
__device__ __forceinline__ uint32_t swz(uint32_t off) {  // SW128 swizzle
    return off ^ ((off >> 3) & 0x70);
}
__device__ __forceinline__ void tma2d(uint32_t dst, const CUtensorMap* map,
                                      int x, int y, uint32_t mb) {
    asm volatile(
        "cp.async.bulk.tensor.2d.shared::cta.global.tile.mbarrier::complete_tx::bytes "
        "[%0], [%1, {%2, %3}], [%4];"
        :: "r"(dst), "l"(map), "r"(x), "r"(y), "r"(mb) : "memory");
}
__device__ __forceinline__ void mbar_wait(uint32_t mb, int phase) {
    asm volatile(
        "{\n\t.reg .pred P;\n\t"
        "W_%=:\n\t"
        "mbarrier.try_wait.parity.acquire.cta.shared::cta.b64 P, [%0], %1, 0x989680;\n\t"
        "@P bra.uni D_%=;\n\t"
        "bra.uni W_%=;\n\t"
        "D_%=:\n\t}"
        :: "r"(mb), "r"(phase) : "memory");
}

#define MMA_16816(dd, aa, b0r, b1r)                                          \
    asm volatile("mma.sync.aligned.m16n8k16.row.col.f32.f16.f16.f32 "        \
        "{%0,%1,%2,%3},{%4,%5,%6,%7},{%8,%9},{%0,%1,%2,%3};"                 \
        : "+f"(dd[0]), "+f"(dd[1]), "+f"(dd[2]), "+f"(dd[3])                 \
        : "r"(aa[0]), "r"(aa[1]), "r"(aa[2]), "r"(aa[3]), "r"(b0r), "r"(b1r))

// ---------------- prep kernels ----------------
// symmetrize triu(raw,1)+T, scale, split limbs -> out[i][colOff + j], ld=KTOT
__global__ void k_sym_split(const float* __restrict__ raw, int n,
                            __half* __restrict__ o0, __half* __restrict__ o1,
                            int colOff) {
    __shared__ float tA[32][33], tB[32][33];
    int bi = blockIdx.y * 32, bj = blockIdx.x * 32;
    int tx = threadIdx.x, ty = threadIdx.y;
#pragma unroll
    for (int j = 0; j < 32; j += 8) {
        tA[ty + j][tx] = raw[(size_t)(bi + ty + j) * n + bj + tx];
        tB[ty + j][tx] = raw[(size_t)(bj + ty + j) * n + bi + tx];
    }
    __syncthreads();
#pragma unroll
    for (int j = 0; j < 32; j += 8) {
        int i = bi + ty + j, jj = bj + tx;
        float wv = (i < jj) ? tA[ty + j][tx] : ((i > jj) ? tB[tx][ty + j] : 0.0f);
        __half h0, h1; split_w(wv, h0, h1);
        o0[(size_t)i * KTOT + colOff + jj] = h0;
        o1[(size_t)i * KTOT + colOff + jj] = h1;
    }
}

// vis_hid -> Wv[v][VS+h] and Wh[h][v]
__global__ void k_vh_split(const float* __restrict__ vh,
                           __half* __restrict__ wv0, __half* __restrict__ wv1,
                           __half* __restrict__ wh0, __half* __restrict__ wh1) {
    __shared__ float tile[32][33];
    int bh = blockIdx.x * 32, bv = blockIdx.y * 32;
    int tx = threadIdx.x, ty = threadIdx.y;
#pragma unroll
    for (int j = 0; j < 32; j += 8)
        tile[ty + j][tx] = vh[(size_t)(bv + ty + j) * HS + bh + tx];
    __syncthreads();
#pragma unroll
    for (int j = 0; j < 32; j += 8) {
        __half h0, h1;
        split_w(tile[ty + j][tx], h0, h1);
        wv0[(size_t)(bv + ty + j) * KTOT + VS + bh + tx] = h0;
        wv1[(size_t)(bv + ty + j) * KTOT + VS + bh + tx] = h1;
        split_w(tile[tx][ty + j], h0, h1);
        wh0[(size_t)(bh + ty + j) * KTOT + bv + tx] = h0;
        wh1[(size_t)(bh + ty + j) * KTOT + bv + tx] = h1;
    }
}

__global__ void k_init(const float* __restrict__ x,
                       float* __restrict__ visF, float* __restrict__ hidF,
                       __half* __restrict__ S0, __half* __restrict__ S1) {
    int idx = blockIdx.x * blockDim.x + threadIdx.x;
    if (idx < NB * VS) {
        int b = idx >> 12, v = idx & (VS - 1);
        float val = x[idx];
        visF[v * NB + b] = val;
        __half h0 = __float2half_rn(val);
        __half h1 = __float2half_rn(val - __half2float(h0));
        S0[(size_t)b * KTOT + v] = h0;
        S1[(size_t)b * KTOT + v] = h1;
    }
    if (idx < NB * HS) {
        int b = idx >> 11, h = idx & (HS - 1);
        hidF[idx] = 0.5f;
        S0[(size_t)b * KTOT + VS + h] = __float2half_rn(0.5f);
        S1[(size_t)b * KTOT + VS + h] = __float2half_rn(0.0f);
    }
}

// ---------------- TMA-fed split-fp16 GEMM ----------------
// D[m, b] = sum_k W[m,k]*S[b,k], 3-product 2-limb split, split-K over blockIdx.z
__global__ __launch_bounds__(256, 2)
void gemm_tma(const __grid_constant__ CUtensorMap mA0,
              const __grid_constant__ CUtensorMap mA1,
              const __grid_constant__ CUtensorMap mB0,
              const __grid_constant__ CUtensorMap mB1,
              float* __restrict__ Cbuf, int Mtot, int kPerSlice) {
    extern __shared__ __align__(128) unsigned char smraw[];
    uint64_t* mbar = (uint64_t*)smraw;                // NSTAGE mbarriers
    unsigned char* data = smraw + 1024;

    const int tid = threadIdx.x;
    const int lane = tid & 31;
    const int w = tid >> 5;
    const int wm = (w & 3) * 32;
    const int wn = (w >> 2) * 32;
    const int m_blk = blockIdx.x * MT;
    const int kbeg = blockIdx.z * kPerSlice;
    const int ntiles = kPerSlice / BKT;

    if (tid == 0) {
#pragma unroll
        for (int s = 0; s < NSTAGE; s++)
            asm volatile("mbarrier.init.shared.b64 [%0], 1;"
                         :: "r"(smaddr(mbar + s)) : "memory");
        asm volatile("fence.proxy.async.shared::cta;" ::: "memory");
    }
    __syncthreads();

    auto issue = [&](int t, int st) {
        uint32_t mb = smaddr(mbar + st);
        asm volatile("mbarrier.arrive.expect_tx.shared.b64 _, [%0], %1;"
                     :: "r"(mb), "r"((uint32_t)STAGE_BYTES) : "memory");
        unsigned char* sp = data + (size_t)st * STAGE_BYTES;
        int kx = kbeg + t * BKT;
        tma2d(smaddr(sp),                                   &mA0, kx, m_blk, mb);
        tma2d(smaddr(sp + A_LIMB_BYTES),                    &mA1, kx, m_blk, mb);
        tma2d(smaddr(sp + 2*A_LIMB_BYTES),                  &mB0, kx, 0,     mb);
        tma2d(smaddr(sp + 2*A_LIMB_BYTES + B_LIMB_BYTES),   &mB1, kx, 0,     mb);
    };

    if (tid == 0) {
        issue(0, 0);
        if (ntiles > 1) issue(1, 1);
    }

    float d[2][4][4];
#pragma unroll
    for (int i = 0; i < 2; i++)
#pragma unroll
        for (int j = 0; j < 4; j++)
#pragma unroll
            for (int q = 0; q < 4; q++) d[i][j][q] = 0.0f;

    for (int t = 0; t < ntiles; t++) {
        int st = t & 1;
        int ph = (t >> 1) & 1;
        mbar_wait(smaddr(mbar + st), ph);

        const unsigned char* sp = data + (size_t)st * STAGE_BYTES;
        const unsigned char* A0s = sp;
        const unsigned char* A1s = sp + A_LIMB_BYTES;
        const unsigned char* B0s = sp + 2*A_LIMB_BYTES;
        const unsigned char* B1s = B0s + B_LIMB_BYTES;

#pragma unroll
        for (int ks = 0; ks < BKT; ks += 16) {
            uint32_t af[2][2][4];   // [mtile][limb][4]
#pragma unroll
            for (int mt = 0; mt < 2; mt++) {
                int row = wm + mt * 16 + ((lane >> 3) & 1) * 8 + (lane & 7);
                uint32_t off = swz((uint32_t)row * 128 + (ks + (lane >> 4) * 8) * 2);
                uint32_t a0 = smaddr(A0s + off);
                asm volatile("ldmatrix.sync.aligned.m8n8.x4.shared.b16 {%0,%1,%2,%3},[%4];"
                    : "=r"(af[mt][0][0]), "=r"(af[mt][0][1]),
                      "=r"(af[mt][0][2]), "=r"(af[mt][0][3]) : "r"(a0));
                uint32_t a1 = smaddr(A1s + off);
                asm volatile("ldmatrix.sync.aligned.m8n8.x4.shared.b16 {%0,%1,%2,%3},[%4];"
                    : "=r"(af[mt][1][0]), "=r"(af[mt][1][1]),
                      "=r"(af[mt][1][2]), "=r"(af[mt][1][3]) : "r"(a1));
            }
            uint32_t bf[2][8];      // [limb][nt*4 + r]
#pragma unroll
            for (int nt = 0; nt < 2; nt++) {
                int row = wn + nt * 16 + (lane >> 4) * 8 + (lane & 7);
                uint32_t off = swz((uint32_t)row * 128 + (ks + ((lane >> 3) & 1) * 8) * 2);
                uint32_t b0 = smaddr(B0s + off);
                asm volatile("ldmatrix.sync.aligned.m8n8.x4.shared.b16 {%0,%1,%2,%3},[%4];"
                    : "=r"(bf[0][nt * 4 + 0]), "=r"(bf[0][nt * 4 + 1]),
                      "=r"(bf[0][nt * 4 + 2]), "=r"(bf[0][nt * 4 + 3]) : "r"(b0));
                uint32_t b1 = smaddr(B1s + off);
                asm volatile("ldmatrix.sync.aligned.m8n8.x4.shared.b16 {%0,%1,%2,%3},[%4];"
                    : "=r"(bf[1][nt * 4 + 0]), "=r"(bf[1][nt * 4 + 1]),
                      "=r"(bf[1][nt * 4 + 2]), "=r"(bf[1][nt * 4 + 3]) : "r"(b1));
            }
#pragma unroll
            for (int mt = 0; mt < 2; mt++) {
#pragma unroll
                for (int j = 0; j < 4; j++) {
                    float* dd = d[mt][j];
                    uint32_t b00 = bf[0][j * 2], b01 = bf[0][j * 2 + 1];
                    uint32_t b10 = bf[1][j * 2], b11 = bf[1][j * 2 + 1];
                    MMA_16816(dd, af[mt][0], b00, b01);   // w0*b0
                    MMA_16816(dd, af[mt][0], b10, b11);   // w0*b1
                    MMA_16816(dd, af[mt][1], b00, b01);   // w1*b0
                }
            }
        }
        __syncthreads();
        if (tid == 0 && t + NSTAGE < ntiles) issue(t + NSTAGE, st);
    }

    float* Cz = Cbuf + (size_t)blockIdx.z * Mtot * NB;
#pragma unroll
    for (int mt = 0; mt < 2; mt++) {
#pragma unroll
        for (int j = 0; j < 4; j++) {
            int r = m_blk + wm + mt * 16 + (lane >> 2);
            int c = wn + j * 8 + (lane & 3) * 2;
            *(float2*)&Cz[(size_t)r * NB + c]       = make_float2(d[mt][j][0], d[mt][j][1]);
            *(float2*)&Cz[(size_t)(r + 8) * NB + c] = make_float2(d[mt][j][2], d[mt][j][3]);
        }
    }
}

// ---------------- epilogue ----------------
__global__ void epi(const float* __restrict__ Cbuf, int S, int F,
                    const float* __restrict__ bias,
                    float* __restrict__ stateF,
                    __half* __restrict__ S0, __half* __restrict__ S1, int colBase,
                    int step, const int* __restrict__ steps_ptr,
                    float* __restrict__ finout) {
    int idx = blockIdx.x * blockDim.x + threadIdx.x;
    if (idx >= F * NB) return;
    int f = idx >> 6, b = idx & 63;
    float s = 0.0f;
    for (int z = 0; z < S; z++) s += Cbuf[(size_t)z * F * NB + idx];
    s = s * INV_WSCALE + bias[f];
    float stepsf = (float)(*steps_ptr);
    float temp = 0.01f * (1.0f + 4.0f * expf((-5.0f * (float)step) / stepsf));
    float p = 1.0f / (1.0f + expf(-s / temp));
    float nv = 0.9f * stateF[idx] + 0.1f * p;
    stateF[idx] = nv;
    __half h0 = __float2half_rn(nv);
    __half h1 = __float2half_rn(nv - __half2float(h0));
    S0[(size_t)b * KTOT + colBase + f] = h0;
    S1[(size_t)b * KTOT + colBase + f] = h1;
    if (finout) finout[(size_t)b * F + f] = nv;
}

// ---------------- host: tensor map encode ----------------
typedef CUresult (*EncodeTiledFn)(
    CUtensorMap*, CUtensorMapDataType, cuuint32_t, void*,
    const cuuint64_t*, const cuuint64_t*, const cuuint32_t*, const cuuint32_t*,
    CUtensorMapInterleave, CUtensorMapSwizzle, CUtensorMapL2promotion,
    CUtensorMapFloatOOBfill);

static EncodeTiledFn get_encoder() {
    void* fp = nullptr;
#if CUDART_VERSION >= 12050
    cudaDriverEntryPointQueryResult st;
    cudaGetDriverEntryPointByVersion("cuTensorMapEncodeTiled", &fp, 12000,
                                     cudaEnableDefault, &st);
#else
    cudaDriverEntryPointQueryResult st;
    cudaGetDriverEntryPoint("cuTensorMapEncodeTiled", &fp, cudaEnableDefault, &st);
#endif
    return (EncodeTiledFn)fp;
}

static void make_map(EncodeTiledFn enc, CUtensorMap* m, void* ptr,
                     uint64_t rows, uint32_t boxRows) {
    cuuint64_t dims[2]    = {(cuuint64_t)KTOT, (cuuint64_t)rows};
    cuuint64_t strides[1] = {(cuuint64_t)KTOT * sizeof(__half)};
    cuuint32_t box[2]     = {BKT, boxRows};
    cuuint32_t es[2]      = {1, 1};
    enc(m, CU_TENSOR_MAP_DATA_TYPE_FLOAT16, 2, ptr, dims, strides, box, es,
        CU_TENSOR_MAP_INTERLEAVE_NONE, CU_TENSOR_MAP_SWIZZLE_128B,
        CU_TENSOR_MAP_L2_PROMOTION_L2_128B, CU_TENSOR_MAP_FLOAT_OOB_FILL_NONE);
}

// ---------------- host launcher ----------------
extern "C" void kernel_launch(void* const* d_in, const int* in_sizes, int n_in,
                              void* d_out, int out_size) {
    const float* x        = (const float*)d_in[0];
    const float* vis_bias = (const float*)d_in[1];
    const float* hid_bias = (const float*)d_in[2];
    const float* vis_hid  = (const float*)d_in[3];
    const float* vv_raw   = (const float*)d_in[4];
    const float* hh_raw   = (const float*)d_in[5];
    const int*   steps_p  = (const int*)d_in[6];

    __half *Wv0, *Wv1, *Wh0, *Wh1, *S0, *S1;
    float *visF, *hidF, *D1, *D2;
    cudaGetSymbolAddress((void**)&Wv0, g_Wv0); cudaGetSymbolAddress((void**)&Wv1, g_Wv1);
    cudaGetSymbolAddress((void**)&Wh0, g_Wh0); cudaGetSymbolAddress((void**)&Wh1, g_Wh1);
    cudaGetSymbolAddress((void**)&S0, g_S0);   cudaGetSymbolAddress((void**)&S1, g_S1);
    cudaGetSymbolAddress((void**)&visF, g_visF); cudaGetSymbolAddress((void**)&hidF, g_hidF);
    cudaGetSymbolAddress((void**)&D1, g_D1);   cudaGetSymbolAddress((void**)&D2, g_D2);

    EncodeTiledFn enc = get_encoder();
    CUtensorMap mWv0, mWv1, mWh0, mWh1, mS0, mS1;
    make_map(enc, &mWv0, Wv0, VS, MT);
    make_map(enc, &mWv1, Wv1, VS, MT);
    make_map(enc, &mWh0, Wh0, HS, MT);
    make_map(enc, &mWh1, Wh1, HS, MT);
    make_map(enc, &mS0,  S0,  NB, NB);
    make_map(enc, &mS1,  S1,  NB, NB);

    const int SMEM = 1024 + NSTAGE * STAGE_BYTES;   // 99328
    cudaFuncSetAttribute(gemm_tma, cudaFuncAttributeMaxDynamicSharedMemorySize, SMEM);

    k_sym_split<<<dim3(VS / 32, VS / 32), dim3(32, 8)>>>(vv_raw, VS, Wv0, Wv1, 0);
    k_sym_split<<<dim3(HS / 32, HS / 32), dim3(32, 8)>>>(hh_raw, HS, Wh0, Wh1, VS);
    k_vh_split<<<dim3(HS / 32, VS / 32), dim3(32, 8)>>>(vis_hid, Wv0, Wv1, Wh0, Wh1);
    k_init<<<(NB * VS + 255) / 256, 256>>>(x, visF, hidF, S0, S1);

    for (int i = 0; i < STEPS; i++) {
        // hidden update
        gemm_tma<<<dim3(HS / MT, 1, SPLIT_H), 256, SMEM>>>(
            mWh0, mWh1, mS0, mS1, D1, HS, KTOT / SPLIT_H);
        epi<<<(HS * NB + 255) / 256, 256>>>(
            D1, SPLIT_H, HS, hid_bias, hidF, S0, S1, VS, i, steps_p, nullptr);

        // visible update
        gemm_tma<<<dim3(VS / MT, 1, SPLIT_V), 256, SMEM>>>(
            mWv0, mWv1, mS0, mS1, D2, VS, KTOT / SPLIT_V);
        epi<<<(VS * NB + 255) / 256, 256>>>(
            D2, SPLIT_V, VS, vis_bias, visF, S0, S1, 0, i, steps_p,
            (i == STEPS - 1) ? (float*)d_out : nullptr);
    }
}

// round 10
// speedup vs baseline: 3.7374x; 1.0470x over previous
#include <cuda_runtime.h>
#include <cuda.h>
#include <cuda_fp16.h>
#include <stdint.h>
#include <math.h>

#define VS 4096
#define HS 2048
#define NB 64
#define STEPS 100
#define SPLIT_H 16
#define SPLIT_V 8
#define KTOT (VS + HS)

#define MT 128        // M tile per CTA
#define BKT 64        // K per tile (64 halves = 128B rows, SW128)
#define NSTAGE 2
#define WSCALE 64.0f
#define INV_WSCALE (1.0f/64.0f)

#define A_LIMB_BYTES (MT * BKT * 2)            // 16384
#define B_LIMB_BYTES (NB * BKT * 2)            // 8192
#define STAGE_BYTES  (2*A_LIMB_BYTES + 2*B_LIMB_BYTES)  // 49152

// ---------------- device scratch ----------------
__device__ __align__(1024) __half g_Wv0[(size_t)VS*KTOT], g_Wv1[(size_t)VS*KTOT]; // [v][vv|vh]
__device__ __align__(1024) __half g_Wh0[(size_t)HS*KTOT], g_Wh1[(size_t)HS*KTOT]; // [h][vht|hh]
__device__ __align__(1024) __half g_S0[NB*KTOT], g_S1[NB*KTOT];                   // [b][vis|hid]
__device__ float g_visF[VS*NB], g_hidF[HS*NB];     // fp32 state [feature][batch]
__device__ float g_D1[SPLIT_H*HS*NB];
__device__ float g_D2[SPLIT_V*VS*NB];

// ---------------- helpers ----------------
__device__ __forceinline__ uint32_t smaddr(const void* p) {
    return (uint32_t)__cvta_generic_to_shared(p);
}
__device__ __forceinline__ void split_w(float w, __half& h0, __half& h1) {
    float ws = w * WSCALE;
    h0 = __float2half_rn(ws);
    h1 = __float2half_rn(ws - __half2float(h0));
}
__device__ __forceinline__ uint32_t swz(uint32_t off) {  // SW128 swizzle
    return off ^ ((off >> 3) & 0x70);
}
__device__ __forceinline__ void tma2d(uint32_t dst, const CUtensorMap* map,
                                      int x, int y, uint32_t mb) {
    asm volatile(
        "cp.async.bulk.tensor.2d.shared::cta.global.tile.mbarrier::complete_tx::bytes "
        "[%0], [%1, {%2, %3}], [%4];"
        :: "r"(dst), "l"(map), "r"(x), "r"(y), "r"(mb) : "memory");
}
__device__ __forceinline__ void mbar_wait(uint32_t mb, int phase) {
    asm volatile(
        "{\n\t.reg .pred P;\n\t"
        "W_%=:\n\t"
        "mbarrier.try_wait.parity.acquire.cta.shared::cta.b64 P, [%0], %1, 0x989680;\n\t"
        "@P bra.uni D_%=;\n\t"
        "bra.uni W_%=;\n\t"
        "D_%=:\n\t}"
        :: "r"(mb), "r"(phase) : "memory");
}

#define MMA_16816(dd, aa, b0r, b1r)                                          \
    asm volatile("mma.sync.aligned.m16n8k16.row.col.f32.f16.f16.f32 "        \
        "{%0,%1,%2,%3},{%4,%5,%6,%7},{%8,%9},{%0,%1,%2,%3};"                 \
        : "+f"(dd[0]), "+f"(dd[1]), "+f"(dd[2]), "+f"(dd[3])                 \
        : "r"(aa[0]), "r"(aa[1]), "r"(aa[2]), "r"(aa[3]), "r"(b0r), "r"(b1r))

// ---------------- prep kernels ----------------
// symmetrize triu(raw,1)+T, scale, split limbs -> out[i][colOff + j], ld=KTOT
__global__ void k_sym_split(const float* __restrict__ raw, int n,
                            __half* __restrict__ o0, __half* __restrict__ o1,
                            int colOff) {
    __shared__ float tA[32][33], tB[32][33];
    int bi = blockIdx.y * 32, bj = blockIdx.x * 32;
    int tx = threadIdx.x, ty = threadIdx.y;
#pragma unroll
    for (int j = 0; j < 32; j += 8) {
        tA[ty + j][tx] = raw[(size_t)(bi + ty + j) * n + bj + tx];
        tB[ty + j][tx] = raw[(size_t)(bj + ty + j) * n + bi + tx];
    }
    __syncthreads();
#pragma unroll
    for (int j = 0; j < 32; j += 8) {
        int i = bi + ty + j, jj = bj + tx;
        float wv = (i < jj) ? tA[ty + j][tx] : ((i > jj) ? tB[tx][ty + j] : 0.0f);
        __half h0, h1; split_w(wv, h0, h1);
        o0[(size_t)i * KTOT + colOff + jj] = h0;
        o1[(size_t)i * KTOT + colOff + jj] = h1;
    }
}

// vis_hid -> Wv[v][VS+h] and Wh[h][v]
__global__ void k_vh_split(const float* __restrict__ vh,
                           __half* __restrict__ wv0, __half* __restrict__ wv1,
                           __half* __restrict__ wh0, __half* __restrict__ wh1) {
    __shared__ float tile[32][33];
    int bh = blockIdx.x * 32, bv = blockIdx.y * 32;
    int tx = threadIdx.x, ty = threadIdx.y;
#pragma unroll
    for (int j = 0; j < 32; j += 8)
        tile[ty + j][tx] = vh[(size_t)(bv + ty + j) * HS + bh + tx];
    __syncthreads();
#pragma unroll
    for (int j = 0; j < 32; j += 8) {
        __half h0, h1;
        split_w(tile[ty + j][tx], h0, h1);
        wv0[(size_t)(bv + ty + j) * KTOT + VS + bh + tx] = h0;
        wv1[(size_t)(bv + ty + j) * KTOT + VS + bh + tx] = h1;
        split_w(tile[tx][ty + j], h0, h1);
        wh0[(size_t)(bh + ty + j) * KTOT + bv + tx] = h0;
        wh1[(size_t)(bh + ty + j) * KTOT + bv + tx] = h1;
    }
}

__global__ void k_init(const float* __restrict__ x,
                       float* __restrict__ visF, float* __restrict__ hidF,
                       __half* __restrict__ S0, __half* __restrict__ S1) {
    int idx = blockIdx.x * blockDim.x + threadIdx.x;
    if (idx < NB * VS) {
        int b = idx >> 12, v = idx & (VS - 1);
        float val = x[idx];
        visF[v * NB + b] = val;
        __half h0 = __float2half_rn(val);
        __half h1 = __float2half_rn(val - __half2float(h0));
        S0[(size_t)b * KTOT + v] = h0;
        S1[(size_t)b * KTOT + v] = h1;
    }
    if (idx < NB * HS) {
        int b = idx >> 11, h = idx & (HS - 1);
        hidF[idx] = 0.5f;
        S0[(size_t)b * KTOT + VS + h] = __float2half_rn(0.5f);
        S1[(size_t)b * KTOT + VS + h] = __float2half_rn(0.0f);
    }
}

// ---------------- TMA-fed split-fp16 GEMM (exact R5, proven) ----------------
__global__ __launch_bounds__(256, 2)
void gemm_tma(const __grid_constant__ CUtensorMap mA0,
              const __grid_constant__ CUtensorMap mA1,
              const __grid_constant__ CUtensorMap mB0,
              const __grid_constant__ CUtensorMap mB1,
              float* __restrict__ Cbuf, int Mtot, int kPerSlice) {
    extern __shared__ __align__(128) unsigned char smraw[];
    uint64_t* mbar = (uint64_t*)smraw;                // NSTAGE mbarriers
    unsigned char* data = smraw + 1024;

    const int tid = threadIdx.x;
    const int lane = tid & 31;
    const int w = tid >> 5;
    const int wm = (w & 3) * 32;
    const int wn = (w >> 2) * 32;
    const int m_blk = blockIdx.x * MT;
    const int kbeg = blockIdx.z * kPerSlice;
    const int ntiles = kPerSlice / BKT;

    if (tid == 0) {
#pragma unroll
        for (int s = 0; s < NSTAGE; s++)
            asm volatile("mbarrier.init.shared.b64 [%0], 1;"
                         :: "r"(smaddr(mbar + s)) : "memory");
        asm volatile("fence.proxy.async.shared::cta;" ::: "memory");
    }
    __syncthreads();

    auto issue = [&](int t, int st) {
        uint32_t mb = smaddr(mbar + st);
        asm volatile("mbarrier.arrive.expect_tx.shared.b64 _, [%0], %1;"
                     :: "r"(mb), "r"((uint32_t)STAGE_BYTES) : "memory");
        unsigned char* sp = data + (size_t)st * STAGE_BYTES;
        int kx = kbeg + t * BKT;
        tma2d(smaddr(sp),                                   &mA0, kx, m_blk, mb);
        tma2d(smaddr(sp + A_LIMB_BYTES),                    &mA1, kx, m_blk, mb);
        tma2d(smaddr(sp + 2*A_LIMB_BYTES),                  &mB0, kx, 0,     mb);
        tma2d(smaddr(sp + 2*A_LIMB_BYTES + B_LIMB_BYTES),   &mB1, kx, 0,     mb);
    };

    if (tid == 0) {
        issue(0, 0);
        if (ntiles > 1) issue(1, 1);
    }

    float d[2][4][4];
#pragma unroll
    for (int i = 0; i < 2; i++)
#pragma unroll
        for (int j = 0; j < 4; j++)
#pragma unroll
            for (int q = 0; q < 4; q++) d[i][j][q] = 0.0f;

    for (int t = 0; t < ntiles; t++) {
        int st = t & 1;
        int ph = (t >> 1) & 1;
        mbar_wait(smaddr(mbar + st), ph);

        const unsigned char* sp = data + (size_t)st * STAGE_BYTES;
        const unsigned char* A0s = sp;
        const unsigned char* A1s = sp + A_LIMB_BYTES;
        const unsigned char* B0s = sp + 2*A_LIMB_BYTES;
        const unsigned char* B1s = B0s + B_LIMB_BYTES;

#pragma unroll
        for (int ks = 0; ks < BKT; ks += 16) {
            uint32_t af[2][2][4];   // [mtile][limb][4]
#pragma unroll
            for (int mt = 0; mt < 2; mt++) {
                int row = wm + mt * 16 + ((lane >> 3) & 1) * 8 + (lane & 7);
                uint32_t off = swz((uint32_t)row * 128 + (ks + (lane >> 4) * 8) * 2);
                uint32_t a0 = smaddr(A0s + off);
                asm volatile("ldmatrix.sync.aligned.m8n8.x4.shared.b16 {%0,%1,%2,%3},[%4];"
                    : "=r"(af[mt][0][0]), "=r"(af[mt][0][1]),
                      "=r"(af[mt][0][2]), "=r"(af[mt][0][3]) : "r"(a0));
                uint32_t a1 = smaddr(A1s + off);
                asm volatile("ldmatrix.sync.aligned.m8n8.x4.shared.b16 {%0,%1,%2,%3},[%4];"
                    : "=r"(af[mt][1][0]), "=r"(af[mt][1][1]),
                      "=r"(af[mt][1][2]), "=r"(af[mt][1][3]) : "r"(a1));
            }
            uint32_t bf[2][8];      // [limb][nt*4 + r]
#pragma unroll
            for (int nt = 0; nt < 2; nt++) {
                int row = wn + nt * 16 + (lane >> 4) * 8 + (lane & 7);
                uint32_t off = swz((uint32_t)row * 128 + (ks + ((lane >> 3) & 1) * 8) * 2);
                uint32_t b0 = smaddr(B0s + off);
                asm volatile("ldmatrix.sync.aligned.m8n8.x4.shared.b16 {%0,%1,%2,%3},[%4];"
                    : "=r"(bf[0][nt * 4 + 0]), "=r"(bf[0][nt * 4 + 1]),
                      "=r"(bf[0][nt * 4 + 2]), "=r"(bf[0][nt * 4 + 3]) : "r"(b0));
                uint32_t b1 = smaddr(B1s + off);
                asm volatile("ldmatrix.sync.aligned.m8n8.x4.shared.b16 {%0,%1,%2,%3},[%4];"
                    : "=r"(bf[1][nt * 4 + 0]), "=r"(bf[1][nt * 4 + 1]),
                      "=r"(bf[1][nt * 4 + 2]), "=r"(bf[1][nt * 4 + 3]) : "r"(b1));
            }
#pragma unroll
            for (int mt = 0; mt < 2; mt++) {
#pragma unroll
                for (int j = 0; j < 4; j++) {
                    float* dd = d[mt][j];
                    uint32_t b00 = bf[0][j * 2], b01 = bf[0][j * 2 + 1];
                    uint32_t b10 = bf[1][j * 2], b11 = bf[1][j * 2 + 1];
                    MMA_16816(dd, af[mt][0], b00, b01);   // w0*b0
                    MMA_16816(dd, af[mt][0], b10, b11);   // w0*b1
                    MMA_16816(dd, af[mt][1], b00, b01);   // w1*b0
                }
            }
        }
        __syncthreads();
        if (tid == 0 && t + NSTAGE < ntiles) issue(t + NSTAGE, st);
    }

    float* Cz = Cbuf + (size_t)blockIdx.z * Mtot * NB;
#pragma unroll
    for (int mt = 0; mt < 2; mt++) {
#pragma unroll
        for (int j = 0; j < 4; j++) {
            int r = m_blk + wm + mt * 16 + (lane >> 2);
            int c = wn + j * 8 + (lane & 3) * 2;
            *(float2*)&Cz[(size_t)r * NB + c]       = make_float2(d[mt][j][0], d[mt][j][1]);
            *(float2*)&Cz[(size_t)(r + 8) * NB + c] = make_float2(d[mt][j][2], d[mt][j][3]);
        }
    }
}

// ---------------- epilogue (two-phase, smem transpose for coalesced limbs) --
// Block: 256 threads, covers TILE_F=16 features x 64 batch.
// Phase 1 (b-major): coalesced Cbuf/stateF float4, sigmoid/blend, nv -> smem.
// Phase 2 (f-major): coalesced half2 limb stores + float4 finout.
__global__ __launch_bounds__(256)
void epi(const float* __restrict__ Cbuf, int S, int F,
         const float* __restrict__ bias,
         float* __restrict__ stateF,
         __half* __restrict__ S0, __half* __restrict__ S1, int colBase,
         int step, const int* __restrict__ steps_ptr,
         float* __restrict__ finout) {
    __shared__ float nvs[16][65];
    const int t = threadIdx.x;
    const int f0 = blockIdx.x * 16;

    float stepsf = (float)(*steps_ptr);
    float temp = 0.01f * (1.0f + 4.0f * expf((-5.0f * (float)step) / stepsf));

    // phase 1: thread -> (f_local = t>>4, b4 = (t&15)*4)
    {
        int fl = t >> 4;
        int b4 = (t & 15) * 4;
        int f = f0 + fl;
        const float* cb = Cbuf + (size_t)f * NB + b4;
        float4 s = make_float4(0.f, 0.f, 0.f, 0.f);
        for (int z = 0; z < S; z++) {
            float4 v = *(const float4*)(cb + (size_t)z * F * NB);
            s.x += v.x; s.y += v.y; s.z += v.z; s.w += v.w;
        }
        float bi = bias[f];
        s.x = s.x * INV_WSCALE + bi; s.y = s.y * INV_WSCALE + bi;
        s.z = s.z * INV_WSCALE + bi; s.w = s.w * INV_WSCALE + bi;
        float4 old = *(const float4*)&stateF[(size_t)f * NB + b4];
        float4 nv;
        nv.x = 0.9f * old.x + 0.1f / (1.0f + expf(-s.x / temp));
        nv.y = 0.9f * old.y + 0.1f / (1.0f + expf(-s.y / temp));
        nv.z = 0.9f * old.z + 0.1f / (1.0f + expf(-s.z / temp));
        nv.w = 0.9f * old.w + 0.1f / (1.0f + expf(-s.w / temp));
        *(float4*)&stateF[(size_t)f * NB + b4] = nv;
        nvs[fl][b4 + 0] = nv.x;
        nvs[fl][b4 + 1] = nv.y;
        nvs[fl][b4 + 2] = nv.z;
        nvs[fl][b4 + 3] = nv.w;
    }
    __syncthreads();

    // phase 2: thread -> (b = t>>2, fo = (t&3)*4): 4 consecutive f per thread
    {
        int b = t >> 2;
        int fo = (t & 3) * 4;
        float v0 = nvs[fo + 0][b], v1 = nvs[fo + 1][b];
        float v2 = nvs[fo + 2][b], v3 = nvs[fo + 3][b];
        __half h00 = __float2half_rn(v0), h01 = __float2half_rn(v1);
        __half h02 = __float2half_rn(v2), h03 = __float2half_rn(v3);
        __half r0 = __float2half_rn(v0 - __half2float(h00));
        __half r1 = __float2half_rn(v1 - __half2float(h01));
        __half r2 = __float2half_rn(v2 - __half2float(h02));
        __half r3 = __float2half_rn(v3 - __half2float(h03));
        size_t base = (size_t)b * KTOT + colBase + f0 + fo;
        *(__half2*)&S0[base]     = __halves2half2(h00, h01);
        *(__half2*)&S0[base + 2] = __halves2half2(h02, h03);
        *(__half2*)&S1[base]     = __halves2half2(r0, r1);
        *(__half2*)&S1[base + 2] = __halves2half2(r2, r3);
        if (finout) {
            *(float4*)&finout[(size_t)b * F + f0 + fo] = make_float4(v0, v1, v2, v3);
        }
    }
}

// ---------------- host: tensor map encode ----------------
typedef CUresult (*EncodeTiledFn)(
    CUtensorMap*, CUtensorMapDataType, cuuint32_t, void*,
    const cuuint64_t*, const cuuint64_t*, const cuuint32_t*, const cuuint32_t*,
    CUtensorMapInterleave, CUtensorMapSwizzle, CUtensorMapL2promotion,
    CUtensorMapFloatOOBfill);

static EncodeTiledFn get_encoder() {
    void* fp = nullptr;
#if CUDART_VERSION >= 12050
    cudaDriverEntryPointQueryResult st;
    cudaGetDriverEntryPointByVersion("cuTensorMapEncodeTiled", &fp, 12000,
                                     cudaEnableDefault, &st);
#else
    cudaDriverEntryPointQueryResult st;
    cudaGetDriverEntryPoint("cuTensorMapEncodeTiled", &fp, cudaEnableDefault, &st);
#endif
    return (EncodeTiledFn)fp;
}

static void make_map(EncodeTiledFn enc, CUtensorMap* m, void* ptr,
                     uint64_t rows, uint32_t boxRows) {
    cuuint64_t dims[2]    = {(cuuint64_t)KTOT, (cuuint64_t)rows};
    cuuint64_t strides[1] = {(cuuint64_t)KTOT * sizeof(__half)};
    cuuint32_t box[2]     = {BKT, boxRows};
    cuuint32_t es[2]      = {1, 1};
    enc(m, CU_TENSOR_MAP_DATA_TYPE_FLOAT16, 2, ptr, dims, strides, box, es,
        CU_TENSOR_MAP_INTERLEAVE_NONE, CU_TENSOR_MAP_SWIZZLE_128B,
        CU_TENSOR_MAP_L2_PROMOTION_L2_128B, CU_TENSOR_MAP_FLOAT_OOB_FILL_NONE);
}

// ---------------- host launcher ----------------
extern "C" void kernel_launch(void* const* d_in, const int* in_sizes, int n_in,
                              void* d_out, int out_size) {
    const float* x        = (const float*)d_in[0];
    const float* vis_bias = (const float*)d_in[1];
    const float* hid_bias = (const float*)d_in[2];
    const float* vis_hid  = (const float*)d_in[3];
    const float* vv_raw   = (const float*)d_in[4];
    const float* hh_raw   = (const float*)d_in[5];
    const int*   steps_p  = (const int*)d_in[6];

    __half *Wv0, *Wv1, *Wh0, *Wh1, *S0, *S1;
    float *visF, *hidF, *D1, *D2;
    cudaGetSymbolAddress((void**)&Wv0, g_Wv0); cudaGetSymbolAddress((void**)&Wv1, g_Wv1);
    cudaGetSymbolAddress((void**)&Wh0, g_Wh0); cudaGetSymbolAddress((void**)&Wh1, g_Wh1);
    cudaGetSymbolAddress((void**)&S0, g_S0);   cudaGetSymbolAddress((void**)&S1, g_S1);
    cudaGetSymbolAddress((void**)&visF, g_visF); cudaGetSymbolAddress((void**)&hidF, g_hidF);
    cudaGetSymbolAddress((void**)&D1, g_D1);   cudaGetSymbolAddress((void**)&D2, g_D2);

    EncodeTiledFn enc = get_encoder();
    CUtensorMap mWv0, mWv1, mWh0, mWh1, mS0, mS1;
    make_map(enc, &mWv0, Wv0, VS, MT);
    make_map(enc, &mWv1, Wv1, VS, MT);
    make_map(enc, &mWh0, Wh0, HS, MT);
    make_map(enc, &mWh1, Wh1, HS, MT);
    make_map(enc, &mS0,  S0,  NB, NB);
    make_map(enc, &mS1,  S1,  NB, NB);

    const int SMEM = 1024 + NSTAGE * STAGE_BYTES;   // 99328
    cudaFuncSetAttribute(gemm_tma, cudaFuncAttributeMaxDynamicSharedMemorySize, SMEM);

    k_sym_split<<<dim3(VS / 32, VS / 32), dim3(32, 8)>>>(vv_raw, VS, Wv0, Wv1, 0);
    k_sym_split<<<dim3(HS / 32, HS / 32), dim3(32, 8)>>>(hh_raw, HS, Wh0, Wh1, VS);
    k_vh_split<<<dim3(HS / 32, VS / 32), dim3(32, 8)>>>(vis_hid, Wv0, Wv1, Wh0, Wh1);
    k_init<<<(NB * VS + 255) / 256, 256>>>(x, visF, hidF, S0, S1);

    for (int i = 0; i < STEPS; i++) {
        // hidden update
        gemm_tma<<<dim3(HS / MT, 1, SPLIT_H), 256, SMEM>>>(
            mWh0, mWh1, mS0, mS1, D1, HS, KTOT / SPLIT_H);
        epi<<<HS / 16, 256>>>(
            D1, SPLIT_H, HS, hid_bias, hidF, S0, S1, VS, i, steps_p, nullptr);

        // visible update
        gemm_tma<<<dim3(VS / MT, 1, SPLIT_V), 256, SMEM>>>(
            mWv0, mWv1, mS0, mS1, D2, VS, KTOT / SPLIT_V);
        epi<<<VS / 16, 256>>>(
            D2, SPLIT_V, VS, vis_bias, visF, S0, S1, 0, i, steps_p,
            (i == STEPS - 1) ? (float*)d_out : nullptr);
    }
}